// round 13
// baseline (speedup 1.0000x reference)
#include <cuda_runtime.h>
#include <cstdint>

// CondFilterT: per row b (BATCH=16384):
//   e = table[inp[b,0]]  (64 fp32)   -> out[b, 0:64] raw
//   for c in 0..49: v = table[inp[b,1+c]]
//     filtered = v * dot(e,v) / (||e|| * ||v||^2)  -> out[b, 64+64c : 64+64(c+1)]
//
// R12: R11's double-buffered pipeline at HIGH occupancy. Stage size U=3
// (24 regs of load buffers instead of 32) + __launch_bounds__(128,10)
// -> <=48 regs, 40 warps/SM (R11 was 64 regs / 32 warps). Extra warps
// cover the shuffle/store windows where each warp has no loads in flight —
// the remaining LTS starvation gap (we're at ~87% of the ~6300 B/cyc cap).

#define CF_BATCH  16384
#define CF_NCONDS 50
#define CF_EMB    64
#define CF_ROWLEN (CF_EMB * (1 + CF_NCONDS))   // 3264 floats per output row

#define ROWS_PER_BLOCK 8                        // 4 warps x 2 rows
#define IDX_PITCH 52

__global__ __launch_bounds__(128, 10)
void condfilter_kernel(const int* __restrict__ inp,
                       const float* __restrict__ table,
                       float* __restrict__ out)
{
    const unsigned FULL = 0xFFFFFFFFu;
    __shared__ int sidx[ROWS_PER_BLOCK][IDX_PITCH];

    const int tid = threadIdx.x;

    // ---- cooperative coalesced load of this block's 8x51 indices ----
    {
        const int* gsrc = inp + (size_t)blockIdx.x * ROWS_PER_BLOCK * (1 + CF_NCONDS);
        for (int i = tid; i < ROWS_PER_BLOCK * (1 + CF_NCONDS); i += 128)
            sidx[i / (1 + CF_NCONDS)][i % (1 + CF_NCONDS)] = gsrc[i];
    }
    __syncthreads();

    const int hl    = tid & 15;                 // lane within half-warp
    const int rib   = tid >> 4;                 // row within block (0..7)
    const int rowid = blockIdx.x * ROWS_PER_BLOCK + rib;
    const int* __restrict__ myidx = &sidx[rib][0];

    const float4* __restrict__ tab = (const float4*)table;   // 16 float4 / row

    // ---- event embedding + inverse norm (reduce over 16 lanes) ----
    const int e_idx = myidx[0];                 // broadcast LDS
    const float4 e = __ldg(tab + (size_t)e_idx * (CF_EMB / 4) + hl);
    float ss = e.x * e.x + e.y * e.y + e.z * e.z + e.w * e.w;
    #pragma unroll
    for (int o = 8; o > 0; o >>= 1) ss += __shfl_xor_sync(FULL, ss, o);
    const float e_inv = rsqrtf(ss);

    float4* orow = (float4*)(out + (size_t)rowid * CF_ROWLEN);
    __stcs(orow + hl, e);   // raw event embedding, 256B coalesced, evict-first

    // ---- reduce + scale + store U conditions held in v[] ----
    auto process = [&](const float4* v, int c0, int U_active) {
        float s1[3], s2[3];
        #pragma unroll
        for (int u = 0; u < 3; u++) {
            if (u >= U_active) break;
            s1[u] = v[u].x * v[u].x + v[u].y * v[u].y
                  + v[u].z * v[u].z + v[u].w * v[u].w;      // ||v||^2
            s2[u] = e.x * v[u].x + e.y * v[u].y
                  + e.z * v[u].z + e.w * v[u].w;            // dot(e,v)
        }
        #pragma unroll
        for (int o = 8; o > 0; o >>= 1) {
            #pragma unroll
            for (int u = 0; u < 3; u++) {
                if (u >= U_active) break;
                s1[u] += __shfl_xor_sync(FULL, s1[u], o);
                s2[u] += __shfl_xor_sync(FULL, s2[u], o);
            }
        }
        #pragma unroll
        for (int u = 0; u < 3; u++) {
            if (u >= U_active) break;
            const float sc = __fdividef(s2[u] * e_inv, s1[u]);   // score/||v||
            float4 w;
            w.x = v[u].x * sc;
            w.y = v[u].y * sc;
            w.z = v[u].z * sc;
            w.w = v[u].w * sc;
            __stcs(orow + 16 + (size_t)(c0 + u) * 16 + hl, w);   // coalesced
        }
    };

    // ---- software-pipelined condition loop ----
    // 50 conds = 16 batches of 3 (conds 0..47) + tail of 2 (48,49)
    float4 cur[3];
    #pragma unroll
    for (int u = 0; u < 3; u++)
        cur[u] = __ldg(tab + (size_t)myidx[1 + u] * (CF_EMB / 4) + hl);

    // 15 steady iterations: prefetch next batch, process current
    for (int c0 = 0; c0 < 45; c0 += 3) {
        float4 nxt[3];
        #pragma unroll
        for (int u = 0; u < 3; u++)
            nxt[u] = __ldg(tab + (size_t)myidx[1 + c0 + 3 + u] * (CF_EMB / 4) + hl);
        process(cur, c0, 3);
        #pragma unroll
        for (int u = 0; u < 3; u++) cur[u] = nxt[u];
    }

    // penultimate: prefetch tail (2 conds), process batch at 45
    {
        float4 nxt[3];
        #pragma unroll
        for (int u = 0; u < 2; u++)
            nxt[u] = __ldg(tab + (size_t)myidx[1 + 48 + u] * (CF_EMB / 4) + hl);
        process(cur, 45, 3);
        cur[0] = nxt[0];
        cur[1] = nxt[1];
    }

    // tail: conds 48, 49
    process(cur, 48, 2);
}

extern "C" void kernel_launch(void* const* d_in, const int* in_sizes, int n_in,
                              void* d_out, int out_size)
{
    const int*   inp   = (const int*)d_in[0];     // (16384, 51) int32
    const float* table = (const float*)d_in[1];   // (100002, 64) float32
    float*       out   = (float*)d_out;           // (16384, 3264) float32

    const int grid = CF_BATCH / ROWS_PER_BLOCK;   // 2048 (exact)
    condfilter_kernel<<<grid, 128>>>(inp, table, out);
}

// round 14
// speedup vs baseline: 1.0471x; 1.0471x over previous
#include <cuda_runtime.h>
#include <cstdint>

// CondFilterT: per row b (BATCH=16384):
//   e = table[inp[b,0]]  (64 fp32)   -> out[b, 0:64] raw
//   for c in 0..49: v = table[inp[b,1+c]]
//     filtered = v * dot(e,v) / (||e|| * ||v||^2)  -> out[b, 64+64c : 64+64(c+1)]
//
// R13: R11's double-buffered half-warp pipeline, stage U=5 (deeper MLP).
// Evidence: MLP/warp 4 -> 40.5us, 3 -> 42.5us; occupancy changes were
// neutral-to-negative. So trade warps for in-flight loads: cur5+nxt5
// buffers (~72 regs, 28 warps/SM) -> outstanding-load product +10%.
// 50 conds = 10 batches of 5: no tail code, tight I$ body.

#define CF_BATCH  16384
#define CF_NCONDS 50
#define CF_EMB    64
#define CF_ROWLEN (CF_EMB * (1 + CF_NCONDS))   // 3264 floats per output row

#define ROWS_PER_BLOCK 8                        // 4 warps x 2 rows
#define IDX_PITCH 52

__global__ __launch_bounds__(128, 7)
void condfilter_kernel(const int* __restrict__ inp,
                       const float* __restrict__ table,
                       float* __restrict__ out)
{
    const unsigned FULL = 0xFFFFFFFFu;
    __shared__ int sidx[ROWS_PER_BLOCK][IDX_PITCH];

    const int tid = threadIdx.x;

    // ---- cooperative coalesced load of this block's 8x51 indices ----
    {
        const int* gsrc = inp + (size_t)blockIdx.x * ROWS_PER_BLOCK * (1 + CF_NCONDS);
        for (int i = tid; i < ROWS_PER_BLOCK * (1 + CF_NCONDS); i += 128)
            sidx[i / (1 + CF_NCONDS)][i % (1 + CF_NCONDS)] = gsrc[i];
    }
    __syncthreads();

    const int hl    = tid & 15;                 // lane within half-warp
    const int rib   = tid >> 4;                 // row within block (0..7)
    const int rowid = blockIdx.x * ROWS_PER_BLOCK + rib;
    const int* __restrict__ myidx = &sidx[rib][0];

    const float4* __restrict__ tab = (const float4*)table;   // 16 float4 / row

    // ---- event embedding + inverse norm (reduce over 16 lanes) ----
    const int e_idx = myidx[0];                 // broadcast LDS
    const float4 e = __ldg(tab + (size_t)e_idx * (CF_EMB / 4) + hl);
    float ss = e.x * e.x + e.y * e.y + e.z * e.z + e.w * e.w;
    #pragma unroll
    for (int o = 8; o > 0; o >>= 1) ss += __shfl_xor_sync(FULL, ss, o);
    const float e_inv = rsqrtf(ss);

    float4* orow = (float4*)(out + (size_t)rowid * CF_ROWLEN);
    __stcs(orow + hl, e);   // raw event embedding, 256B coalesced, evict-first

    // ---- reduce + scale + store one batch of 5 conditions held in v[] ----
    auto process = [&](const float4* v, int c0) {
        float s1[5], s2[5];
        #pragma unroll
        for (int u = 0; u < 5; u++) {
            s1[u] = v[u].x * v[u].x + v[u].y * v[u].y
                  + v[u].z * v[u].z + v[u].w * v[u].w;      // ||v||^2
            s2[u] = e.x * v[u].x + e.y * v[u].y
                  + e.z * v[u].z + e.w * v[u].w;            // dot(e,v)
        }
        #pragma unroll
        for (int o = 8; o > 0; o >>= 1) {
            #pragma unroll
            for (int u = 0; u < 5; u++) {
                s1[u] += __shfl_xor_sync(FULL, s1[u], o);
                s2[u] += __shfl_xor_sync(FULL, s2[u], o);
            }
        }
        #pragma unroll
        for (int u = 0; u < 5; u++) {
            const float sc = __fdividef(s2[u] * e_inv, s1[u]);   // score/||v||
            float4 w;
            w.x = v[u].x * sc;
            w.y = v[u].y * sc;
            w.z = v[u].z * sc;
            w.w = v[u].w * sc;
            __stcs(orow + 16 + (size_t)(c0 + u) * 16 + hl, w);   // coalesced
        }
    };

    // ---- software-pipelined condition loop: 10 batches of 5, no tail ----
    float4 cur[5];
    #pragma unroll
    for (int u = 0; u < 5; u++)
        cur[u] = __ldg(tab + (size_t)myidx[1 + u] * (CF_EMB / 4) + hl);

    for (int c0 = 0; c0 < CF_NCONDS - 5; c0 += 5) {
        float4 nxt[5];
        #pragma unroll
        for (int u = 0; u < 5; u++)
            nxt[u] = __ldg(tab + (size_t)myidx[1 + c0 + 5 + u] * (CF_EMB / 4) + hl);
        process(cur, c0);
        #pragma unroll
        for (int u = 0; u < 5; u++) cur[u] = nxt[u];
    }

    process(cur, CF_NCONDS - 5);   // final batch (conds 45..49)
}

extern "C" void kernel_launch(void* const* d_in, const int* in_sizes, int n_in,
                              void* d_out, int out_size)
{
    const int*   inp   = (const int*)d_in[0];     // (16384, 51) int32
    const float* table = (const float*)d_in[1];   // (100002, 64) float32
    float*       out   = (float*)d_out;           // (16384, 3264) float32

    const int grid = CF_BATCH / ROWS_PER_BLOCK;   // 2048 (exact)
    condfilter_kernel<<<grid, 128>>>(inp, table, out);
}

// round 15
// speedup vs baseline: 1.0572x; 1.0097x over previous
#include <cuda_runtime.h>
#include <cstdint>

// CondFilterT: per row b (BATCH=16384):
//   e = table[inp[b,0]]  (64 fp32)   -> out[b, 0:64] raw
//   for c in 0..49: v = table[inp[b,1+c]]
//     filtered = v * dot(e,v) / (||e|| * ||v||^2)  -> out[b, 64+64c : 64+64(c+1)]
//
// R14: prefetch DISTANCE 2 (triple buffer, U=3). During every process
// window the warp has 6 gather lines in flight (R13: 5) and each load gets
// ~2 process-phases of latency cover. Buffer regs 36 (< R13's 40) so
// occupancy recovers to ~40%. MLP-depth curve so far: 3->42.5, 4->40.5,
// 5->40.2 us; this pushes effective depth past 5 without the reg blowout.

#define CF_BATCH  16384
#define CF_NCONDS 50
#define CF_EMB    64
#define CF_ROWLEN (CF_EMB * (1 + CF_NCONDS))   // 3264 floats per output row

#define ROWS_PER_BLOCK 8                        // 4 warps x 2 rows
#define IDX_PITCH 52

__global__ __launch_bounds__(128, 8)
void condfilter_kernel(const int* __restrict__ inp,
                       const float* __restrict__ table,
                       float* __restrict__ out)
{
    const unsigned FULL = 0xFFFFFFFFu;
    __shared__ int sidx[ROWS_PER_BLOCK][IDX_PITCH];

    const int tid = threadIdx.x;

    // ---- cooperative coalesced load of this block's 8x51 indices ----
    {
        const int* gsrc = inp + (size_t)blockIdx.x * ROWS_PER_BLOCK * (1 + CF_NCONDS);
        for (int i = tid; i < ROWS_PER_BLOCK * (1 + CF_NCONDS); i += 128)
            sidx[i / (1 + CF_NCONDS)][i % (1 + CF_NCONDS)] = gsrc[i];
    }
    __syncthreads();

    const int hl    = tid & 15;                 // lane within half-warp
    const int rib   = tid >> 4;                 // row within block (0..7)
    const int rowid = blockIdx.x * ROWS_PER_BLOCK + rib;
    const int* __restrict__ myidx = &sidx[rib][0];

    const float4* __restrict__ tab = (const float4*)table;   // 16 float4 / row

    // ---- event embedding + inverse norm (reduce over 16 lanes) ----
    const int e_idx = myidx[0];                 // broadcast LDS
    const float4 e = __ldg(tab + (size_t)e_idx * (CF_EMB / 4) + hl);
    float ss = e.x * e.x + e.y * e.y + e.z * e.z + e.w * e.w;
    #pragma unroll
    for (int o = 8; o > 0; o >>= 1) ss += __shfl_xor_sync(FULL, ss, o);
    const float e_inv = rsqrtf(ss);

    float4* orow = (float4*)(out + (size_t)rowid * CF_ROWLEN);
    __stcs(orow + hl, e);   // raw event embedding, 256B coalesced, evict-first

    // ---- reduce + scale + store U conditions held in v[] ----
    auto process = [&](const float4* v, int c0, int U_active) {
        float s1[3], s2[3];
        #pragma unroll
        for (int u = 0; u < 3; u++) {
            if (u >= U_active) break;
            s1[u] = v[u].x * v[u].x + v[u].y * v[u].y
                  + v[u].z * v[u].z + v[u].w * v[u].w;      // ||v||^2
            s2[u] = e.x * v[u].x + e.y * v[u].y
                  + e.z * v[u].z + e.w * v[u].w;            // dot(e,v)
        }
        #pragma unroll
        for (int o = 8; o > 0; o >>= 1) {
            #pragma unroll
            for (int u = 0; u < 3; u++) {
                if (u >= U_active) break;
                s1[u] += __shfl_xor_sync(FULL, s1[u], o);
                s2[u] += __shfl_xor_sync(FULL, s2[u], o);
            }
        }
        #pragma unroll
        for (int u = 0; u < 3; u++) {
            if (u >= U_active) break;
            const float sc = __fdividef(s2[u] * e_inv, s1[u]);   // score/||v||
            float4 w;
            w.x = v[u].x * sc;
            w.y = v[u].y * sc;
            w.z = v[u].z * sc;
            w.w = v[u].w * sc;
            __stcs(orow + 16 + (size_t)(c0 + u) * 16 + hl, w);   // coalesced
        }
    };

    auto load3 = [&](float4* b, int c0, int n) {
        #pragma unroll
        for (int u = 0; u < 3; u++) {
            if (u >= n) break;
            b[u] = __ldg(tab + (size_t)myidx[1 + c0 + u] * (CF_EMB / 4) + hl);
        }
    };

    // ---- distance-2 pipelined loop: 16 batches of 3 + tail of 2 ----
    float4 b0[3], b1[3];
    load3(b0, 0, 3);                 // batch @0  (conds 0..2)
    load3(b1, 3, 3);                 // batch @3  (conds 3..5)

    // steady: c0 = 0,3,...,39 — prefetch batch @c0+6, process batch @c0
    for (int c0 = 0; c0 < 42; c0 += 3) {
        float4 b2[3];
        load3(b2, c0 + 6, 3);        // prefetches conds 6..47
        process(b0, c0, 3);
        #pragma unroll
        for (int u = 0; u < 3; u++) { b0[u] = b1[u]; b1[u] = b2[u]; }
    }

    // c0 = 42: prefetch the 2-cond tail (48,49), process @42
    {
        float4 b2[3];
        load3(b2, 48, 2);
        process(b0, 42, 3);
        #pragma unroll
        for (int u = 0; u < 3; u++) { b0[u] = b1[u]; b1[u] = b2[u]; }
    }

    process(b0, 45, 3);              // conds 45..47
    process(b1, 48, 2);              // conds 48..49
}

extern "C" void kernel_launch(void* const* d_in, const int* in_sizes, int n_in,
                              void* d_out, int out_size)
{
    const int*   inp   = (const int*)d_in[0];     // (16384, 51) int32
    const float* table = (const float*)d_in[1];   // (100002, 64) float32
    float*       out   = (float*)d_out;           // (16384, 3264) float32

    const int grid = CF_BATCH / ROWS_PER_BLOCK;   // 2048 (exact)
    condfilter_kernel<<<grid, 128>>>(inp, table, out);
}